// round 1
// baseline (speedup 1.0000x reference)
#include <cuda_runtime.h>

#define NB  4
#define NH  4
#define NN  2048
#define FIN 128
#define ND  32
#define BHD (NB*NH)

// scratch (device globals; no allocation allowed)
__device__ float g_Wh [BHD*NN*ND];        // per-(b,h) projected features
__device__ float g_Wh1[BHD*NN];
__device__ float g_Wh2[BHD*NN];
__device__ float g_Sneg[BHD*(NN+1)*ND];   // prefix sums of exp(0.2*w2)*Wh (sorted order)
__device__ float g_Spos[BHD*(NN+1)*ND];   // suffix sums of exp(w2)*Wh (sorted order)

// ---------------- kernel 1: Wh = x @ W[h], Wh1 = Wh.a1, Wh2 = Wh.a2 ----------------
__global__ void __launch_bounds__(256) k1(const float* __restrict__ x,
                                          const float* __restrict__ W,
                                          const float* __restrict__ a) {
    __shared__ float Ws[FIN*ND];
    __shared__ float a1s[ND], a2s[ND];
    const int h = blockIdx.y, b = blockIdx.z;
    const int tid = threadIdx.x;
    for (int i = tid; i < FIN*ND; i += 256) Ws[i] = W[h*FIN*ND + i];
    if (tid < 2*ND) {
        float v = a[h*2*ND + tid];
        if (tid < ND) a1s[tid] = v; else a2s[tid-ND] = v;
    }
    __syncthreads();

    const int warp = tid >> 5, lane = tid & 31;
    const int n = blockIdx.x * 8 + warp;            // warp per row
    const float* xr = x + ((size_t)(b*NN + n))*FIN;
    float xv[4];
    #pragma unroll
    for (int q = 0; q < 4; q++) xv[q] = xr[q*32 + lane];

    float acc = 0.f;
    #pragma unroll
    for (int k = 0; k < FIN; k++) {
        float xb = __shfl_sync(0xffffffffu, xv[k >> 5], k & 31);
        acc = fmaf(xb, Ws[k*ND + lane], acc);
    }
    const int bh = b*NH + h;
    g_Wh[((size_t)(bh*NN + n))*ND + lane] = acc;

    float t1 = acc * a1s[lane], t2 = acc * a2s[lane];
    #pragma unroll
    for (int o = 16; o; o >>= 1) {
        t1 += __shfl_xor_sync(0xffffffffu, t1, o);
        t2 += __shfl_xor_sync(0xffffffffu, t2, o);
    }
    if (lane == 0) { g_Wh1[bh*NN + n] = t1; g_Wh2[bh*NN + n] = t2; }
}

__device__ __forceinline__ float warp_incl_scan(float v, int lane) {
    #pragma unroll
    for (int o = 1; o < 32; o <<= 1) {
        float u = __shfl_up_sync(0xffffffffu, v, o);
        if (lane >= o) v += u;
    }
    return v;
}

// ---------------- kernel 2: sort + prefix/suffix sums + per-row combine ----------------
__global__ void __launch_bounds__(1024) k2(float* __restrict__ out) {
    __shared__ float w2s[NN];
    __shared__ unsigned short ids[NN];
    __shared__ float pneg[NN+1], ppos[NN+1];
    __shared__ float tile[128][33];
    __shared__ float ew[128];

    const int bh = blockIdx.x;
    const int b = bh / NH, h = bh % NH;
    const int tid = threadIdx.x;
    const int warp = tid >> 5, lane = tid & 31;

    for (int j = tid; j < NN; j += 1024) {
        w2s[j] = g_Wh2[bh*NN + j];
        ids[j] = (unsigned short)j;
    }
    __syncthreads();

    // bitonic sort ascending by w2, carrying original index
    for (int k = 2; k <= NN; k <<= 1) {
        for (int s = k >> 1; s > 0; s >>= 1) {
            #pragma unroll
            for (int tt = 0; tt < 2; tt++) {
                int t = tid + tt*1024;
                int ixj = t ^ s;
                if (ixj > t) {
                    float va = w2s[t], vb = w2s[ixj];
                    bool up = ((t & k) == 0);
                    if (up ? (va > vb) : (va < vb)) {
                        w2s[t] = vb; w2s[ixj] = va;
                        unsigned short tmp = ids[t]; ids[t] = ids[ixj]; ids[ixj] = tmp;
                    }
                }
            }
            __syncthreads();
        }
    }

    // scalar prefix (exp(0.2*w2), forward-exclusive) and suffix (exp(w2), backward-inclusive)
    if (warp == 0) {
        float carry = 0.f;
        for (int t0 = 0; t0 < NN; t0 += 32) {
            float inc = warp_incl_scan(expf(0.2f * w2s[t0 + lane]), lane);
            float exc = __shfl_up_sync(0xffffffffu, inc, 1);
            if (lane == 0) exc = 0.f;
            pneg[t0 + lane] = carry + exc;
            carry += __shfl_sync(0xffffffffu, inc, 31);
        }
        if (lane == 0) pneg[NN] = carry;
    } else if (warp == 1) {
        float carry = 0.f;
        for (int t0 = 0; t0 < NN; t0 += 32) {
            int j = NN - 1 - (t0 + lane);
            float inc = warp_incl_scan(expf(w2s[j]), lane);
            ppos[j] = carry + inc;
            carry += __shfl_sync(0xffffffffu, inc, 31);
        }
        if (lane == 0) ppos[NN] = 0.f;
    }

    // vector forward scan: Sneg[k] = sum_{j<k} exp(0.2*w2_j) * Wh[perm[j]]
    {
        float carry = 0.f;
        for (int tb = 0; tb < NN; tb += 128) {
            __syncthreads();
            if (tid < 128) ew[tid] = expf(0.2f * w2s[tb + tid]);
            #pragma unroll
            for (int q = 0; q < 4; q++) {
                int r = (tid >> 5) + q*32;
                tile[r][lane] = g_Wh[((size_t)(bh*NN) + ids[tb + r])*ND + lane];
            }
            __syncthreads();
            #pragma unroll
            for (int s = 0; s < 4; s++) {
                int jj = s*32 + lane;
                float v = ew[jj] * tile[jj][warp];
                float inc = warp_incl_scan(v, lane);
                float exc = __shfl_up_sync(0xffffffffu, inc, 1);
                if (lane == 0) exc = 0.f;
                tile[jj][warp] = carry + exc;
                carry += __shfl_sync(0xffffffffu, inc, 31);
            }
            __syncthreads();
            #pragma unroll
            for (int q = 0; q < 4; q++) {
                int r = (tid >> 5) + q*32;
                g_Sneg[((size_t)(bh*(NN+1)) + tb + r)*ND + lane] = tile[r][lane];
            }
        }
        if (lane == 0) g_Sneg[((size_t)(bh*(NN+1)) + NN)*ND + warp] = carry;
    }

    // vector backward scan: Spos[k] = sum_{j>=k} exp(w2_j) * Wh[perm[j]]
    {
        float carry = 0.f;
        for (int tb = 0; tb < NN; tb += 128) {
            __syncthreads();
            if (tid < 128) ew[tid] = expf(w2s[NN - 1 - (tb + tid)]);
            #pragma unroll
            for (int q = 0; q < 4; q++) {
                int r = (tid >> 5) + q*32;
                tile[r][lane] = g_Wh[((size_t)(bh*NN) + ids[NN - 1 - (tb + r)])*ND + lane];
            }
            __syncthreads();
            #pragma unroll
            for (int s = 0; s < 4; s++) {
                int mm = s*32 + lane;
                float v = ew[mm] * tile[mm][warp];
                float inc = warp_incl_scan(v, lane);
                tile[mm][warp] = carry + inc;
                carry += __shfl_sync(0xffffffffu, inc, 31);
            }
            __syncthreads();
            #pragma unroll
            for (int q = 0; q < 4; q++) {
                int r = (tid >> 5) + q*32;
                g_Spos[((size_t)(bh*(NN+1)) + (NN - 1 - (tb + r)))*ND + lane] = tile[r][lane];
            }
        }
        if (lane == 0) g_Spos[((size_t)(bh*(NN+1)) + NN)*ND + warp] = 0.f;
    }
    __syncthreads();

    // per-row combine: binary search threshold, blend prefix/suffix, elu, store
    for (int it = 0; it < NN/32; it++) {
        int i = it*32 + warp;
        float w1 = g_Wh1[bh*NN + i];
        float thr = -w1;
        int lo = 0, hi = NN;
        while (lo < hi) {
            int mid = (lo + hi) >> 1;
            if (w2s[mid] <= thr) lo = mid + 1; else hi = mid;
        }
        float f1 = expf(w1), f2 = expf(0.2f * w1);
        size_t base = ((size_t)(bh*(NN+1)) + lo)*ND + lane;
        float num = f2 * g_Sneg[base] + f1 * g_Spos[base];
        float den = f2 * pneg[lo] + f1 * ppos[lo];
        float hv = num / den;
        float r = hv > 0.f ? hv : expm1f(hv);
        out[((size_t)(b*NN + i))*(NH*ND) + h*ND + lane] = r;
    }
}

extern "C" void kernel_launch(void* const* d_in, const int* in_sizes, int n_in,
                              void* d_out, int out_size) {
    (void)in_sizes; (void)n_in; (void)out_size;
    const float* x = (const float*)d_in[0];
    const float* W = (const float*)d_in[1];
    const float* a = (const float*)d_in[2];
    float* out = (float*)d_out;

    dim3 g1(NN/8, NH, NB);
    k1<<<g1, 256>>>(x, W, a);
    k2<<<BHD, 1024>>>(out);
}

// round 2
// speedup vs baseline: 2.3517x; 2.3517x over previous
#include <cuda_runtime.h>

#define NB   4
#define NH   4
#define NN   2048
#define FIN  128
#define ND   32
#define BHD  (NB*NH)
#define NCH  16      // chunks per (b,h)
#define CHSZ 128     // rows per chunk

// scratch (device globals; no allocation allowed)
__device__ float g_Wh  [BHD*NN*ND];
__device__ float g_Wh1 [BHD*NN];
__device__ float g_Wh2 [BHD*NN];
__device__ int   g_perm[BHD*NN];        // sorted pos -> original row
__device__ float g_w2s [BHD*NN];        // sorted w2 keys
__device__ float g_SnegL[BHD*NN*ND];    // per-chunk exclusive prefix of exp(.2 w2)*Wh
__device__ float g_SposL[BHD*NN*ND];    // per-chunk inclusive suffix of exp(w2)*Wh
__device__ float g_CnegT[BHD*NCH*ND];   // chunk total vectors
__device__ float g_CposT[BHD*NCH*ND];
__device__ float g_pnL[BHD*NN];         // scalar local prefix/suffix
__device__ float g_ppL[BHD*NN];
__device__ float g_pnT[BHD*NCH];        // scalar chunk totals
__device__ float g_ppT[BHD*NCH];

__device__ __forceinline__ float warp_incl_scan(float v, int lane) {
    #pragma unroll
    for (int o = 1; o < 32; o <<= 1) {
        float u = __shfl_up_sync(0xffffffffu, v, o);
        if (lane >= o) v += u;
    }
    return v;
}

// ---------------- kernel 1: Wh = x @ W[h], Wh1 = Wh.a1, Wh2 = Wh.a2 ----------------
__global__ void __launch_bounds__(256) k1(const float* __restrict__ x,
                                          const float* __restrict__ W,
                                          const float* __restrict__ a) {
    __shared__ float Ws[FIN*ND];
    __shared__ float a1s[ND], a2s[ND];
    const int h = blockIdx.y, b = blockIdx.z;
    const int tid = threadIdx.x;
    for (int i = tid; i < FIN*ND; i += 256) Ws[i] = W[h*FIN*ND + i];
    if (tid < 2*ND) {
        float v = a[h*2*ND + tid];
        if (tid < ND) a1s[tid] = v; else a2s[tid-ND] = v;
    }
    __syncthreads();

    const int warp = tid >> 5, lane = tid & 31;
    const int n = blockIdx.x * 8 + warp;
    const float* xr = x + ((size_t)(b*NN + n))*FIN;
    float xv[4];
    #pragma unroll
    for (int q = 0; q < 4; q++) xv[q] = xr[q*32 + lane];

    float acc = 0.f;
    #pragma unroll
    for (int k = 0; k < FIN; k++) {
        float xb = __shfl_sync(0xffffffffu, xv[k >> 5], k & 31);
        acc = fmaf(xb, Ws[k*ND + lane], acc);
    }
    const int bh = b*NH + h;
    g_Wh[((size_t)(bh*NN + n))*ND + lane] = acc;

    float t1 = acc * a1s[lane], t2 = acc * a2s[lane];
    #pragma unroll
    for (int o = 16; o; o >>= 1) {
        t1 += __shfl_xor_sync(0xffffffffu, t1, o);
        t2 += __shfl_xor_sync(0xffffffffu, t2, o);
    }
    if (lane == 0) { g_Wh1[bh*NN + n] = t1; g_Wh2[bh*NN + n] = t2; }
}

// ---------------- kernel 2: rank-by-counting "sort" ----------------
__global__ void __launch_bounds__(256) k2rank() {
    __shared__ float4 w2v[NN/4];
    const int bh = blockIdx.y;
    const int tid = threadIdx.x;
    const float* w2 = g_Wh2 + bh*NN;
    for (int j = tid; j < NN/4; j += 256) w2v[j] = ((const float4*)w2)[j];
    __syncthreads();
    const int i = blockIdx.x*256 + tid;
    const float vi = ((const float*)w2v)[i];
    int rank = 0;
    #pragma unroll 8
    for (int j4 = 0; j4 < NN/4; j4++) {
        float4 v = w2v[j4];
        int j = j4*4;
        rank += (v.x < vi) || (v.x == vi && (j+0) < i);
        rank += (v.y < vi) || (v.y == vi && (j+1) < i);
        rank += (v.z < vi) || (v.z == vi && (j+2) < i);
        rank += (v.w < vi) || (v.w == vi && (j+3) < i);
    }
    g_perm[bh*NN + rank] = i;
    g_w2s [bh*NN + rank] = vi;
}

// ---------------- kernel 3: per-chunk local scans + chunk totals ----------------
__global__ void __launch_bounds__(1024) k3() {
    __shared__ float tA[CHSZ][ND+1];
    __shared__ float tB[CHSZ][ND+1];
    __shared__ float ewn[CHSZ], ewp[CHSZ];
    __shared__ int   pr[CHSZ];
    const int c = blockIdx.x, bh = blockIdx.y;
    const int tid = threadIdx.x, warp = tid >> 5, lane = tid & 31;
    const int base = bh*NN + c*CHSZ;

    if (tid < CHSZ) {
        float v = g_w2s[base + tid];
        ewn[tid] = expf(0.2f * v);
        ewp[tid] = expf(v);
        pr[tid]  = g_perm[base + tid];
    }
    __syncthreads();
    #pragma unroll
    for (int q = 0; q < 4; q++) {
        int r = warp + q*32;
        tA[r][lane] = g_Wh[((size_t)(bh*NN) + pr[r])*ND + lane];
    }
    __syncthreads();

    // forward neg scan (exclusive), warp = channel
    {
        float carry = 0.f;
        #pragma unroll
        for (int s = 0; s < 4; s++) {
            int j = s*32 + lane;
            float v = ewn[j] * tA[j][warp];
            float inc = warp_incl_scan(v, lane);
            float exc = __shfl_up_sync(0xffffffffu, inc, 1);
            if (lane == 0) exc = 0.f;
            tB[j][warp] = carry + exc;
            carry += __shfl_sync(0xffffffffu, inc, 31);
        }
        if (lane == 0) g_CnegT[(bh*NCH + c)*ND + warp] = carry;
    }
    __syncthreads();
    #pragma unroll
    for (int q = 0; q < 4; q++) {
        int r = warp + q*32;
        g_SnegL[((size_t)base + r)*ND + lane] = tB[r][lane];
    }
    __syncthreads();

    // backward pos scan (inclusive suffix)
    {
        float carry = 0.f;
        #pragma unroll
        for (int s = 3; s >= 0; s--) {
            int j = s*32 + (31 - lane);       // lane 0 <-> highest j in group
            float v = ewp[j] * tA[j][warp];
            float inc = warp_incl_scan(v, lane);
            tB[j][warp] = carry + inc;
            carry += __shfl_sync(0xffffffffu, inc, 31);
        }
        if (lane == 0) g_CposT[(bh*NCH + c)*ND + warp] = carry;
    }
    __syncthreads();
    #pragma unroll
    for (int q = 0; q < 4; q++) {
        int r = warp + q*32;
        g_SposL[((size_t)base + r)*ND + lane] = tB[r][lane];
    }

    // scalar local scans (warps 0 and 1)
    if (warp == 0) {
        float carry = 0.f;
        #pragma unroll
        for (int s = 0; s < 4; s++) {
            int j = s*32 + lane;
            float inc = warp_incl_scan(ewn[j], lane);
            float exc = __shfl_up_sync(0xffffffffu, inc, 1);
            if (lane == 0) exc = 0.f;
            g_pnL[base + j] = carry + exc;
            carry += __shfl_sync(0xffffffffu, inc, 31);
        }
        if (lane == 0) g_pnT[bh*NCH + c] = carry;
    } else if (warp == 1) {
        float carry = 0.f;
        #pragma unroll
        for (int s = 3; s >= 0; s--) {
            int j = s*32 + (31 - lane);
            float inc = warp_incl_scan(ewp[j], lane);
            g_ppL[base + j] = carry + inc;
            carry += __shfl_sync(0xffffffffu, inc, 31);
        }
        if (lane == 0) g_ppT[bh*NCH + c] = carry;
    }
}

// ---------------- kernel 5: per-row combine ----------------
__global__ void __launch_bounds__(256) k5(float* __restrict__ out) {
    __shared__ float w2s[NN];
    __shared__ float OffN[(NCH+1)*ND];
    __shared__ float OffP[NCH*ND];
    __shared__ float opn[NCH+1], opp[NCH];
    const int seg = blockIdx.x, bh = blockIdx.y;
    const int b = bh >> 2, h = bh & 3;
    const int tid = threadIdx.x, warp = tid >> 5, lane = tid & 31;

    for (int j = tid; j < NN; j += 256) w2s[j] = g_w2s[bh*NN + j];
    if (tid < ND) {
        float s = 0.f;
        for (int c = 0; c < NCH; c++) { OffN[c*ND + tid] = s; s += g_CnegT[(bh*NCH + c)*ND + tid]; }
        OffN[NCH*ND + tid] = s;
    } else if (tid < 2*ND) {
        int ch = tid - ND;
        float s = 0.f;
        for (int c = NCH-1; c >= 0; c--) { OffP[c*ND + ch] = s; s += g_CposT[(bh*NCH + c)*ND + ch]; }
    } else if (tid == 2*ND) {
        float s = 0.f;
        for (int c = 0; c < NCH; c++) { opn[c] = s; s += g_pnT[bh*NCH + c]; }
        opn[NCH] = s;
    } else if (tid == 2*ND + 1) {
        float s = 0.f;
        for (int c = NCH-1; c >= 0; c--) { opp[c] = s; s += g_ppT[bh*NCH + c]; }
    }
    __syncthreads();

    #pragma unroll 4
    for (int r = 0; r < 16; r++) {
        int i = seg*128 + warp*16 + r;
        float w1 = g_Wh1[bh*NN + i];
        float thr = -w1;
        int lo = 0, hi = NN;
        while (lo < hi) { int mid = (lo + hi) >> 1; if (w2s[mid] <= thr) lo = mid + 1; else hi = mid; }
        float f1 = expf(w1), f2 = expf(0.2f * w1);
        float sneg, spos, pn, pp;
        if (lo < NN) {
            int c = lo >> 7;
            size_t ix = ((size_t)(bh*NN) + lo)*ND + lane;
            sneg = g_SnegL[ix] + OffN[c*ND + lane];
            spos = g_SposL[ix] + OffP[c*ND + lane];
            pn = g_pnL[bh*NN + lo] + opn[c];
            pp = g_ppL[bh*NN + lo] + opp[c];
        } else {
            sneg = OffN[NCH*ND + lane]; spos = 0.f;
            pn = opn[NCH]; pp = 0.f;
        }
        float num = f2*sneg + f1*spos;
        float den = f2*pn + f1*pp;
        float hv = num / den;
        float res = hv > 0.f ? hv : expm1f(hv);
        out[((size_t)(b*NN + i))*(NH*ND) + h*ND + lane] = res;
    }
}

extern "C" void kernel_launch(void* const* d_in, const int* in_sizes, int n_in,
                              void* d_out, int out_size) {
    (void)in_sizes; (void)n_in; (void)out_size;
    const float* x = (const float*)d_in[0];
    const float* W = (const float*)d_in[1];
    const float* a = (const float*)d_in[2];
    float* out = (float*)d_out;

    dim3 g1(NN/8, NH, NB);
    k1<<<g1, 256>>>(x, W, a);
    k2rank<<<dim3(NN/256, BHD), 256>>>();
    k3<<<dim3(NCH, BHD), 1024>>>();
    k5<<<dim3(NN/128, BHD), 256>>>(out);
}

// round 3
// speedup vs baseline: 2.8732x; 1.2217x over previous
#include <cuda_runtime.h>

#define NB   4
#define NH   4
#define NN   2048
#define FIN  128
#define ND   32
#define BHD  (NB*NH)
#define NCH  16      // chunks per (b,h)
#define CHSZ 128     // rows per chunk

// scratch (device globals; no allocation allowed)
__device__ float  g_Wh  [BHD*NN*ND];
__device__ float  g_Wh1 [BHD*NN];
__device__ float  g_Wh2 [BHD*NN];
__device__ int    g_perm[BHD*NN];        // sorted pos -> original row
__device__ float  g_w2s [BHD*NN];        // sorted w2 keys
__device__ float  g_SnegL[BHD*NN*ND];    // per-chunk exclusive prefix of exp(.2 w2)*Wh
__device__ float  g_SposL[BHD*NN*ND];    // per-chunk inclusive suffix of exp(w2)*Wh
__device__ float  g_CnegT[BHD*NCH*ND];   // chunk total vectors
__device__ float  g_CposT[BHD*NCH*ND];
__device__ float  g_pnL[BHD*NN];         // scalar local prefix/suffix
__device__ float  g_ppL[BHD*NN];
__device__ float  g_pnT[BHD*NCH];        // scalar chunk totals
__device__ float  g_ppT[BHD*NCH];
__device__ float  g_OffN[BHD*(NCH+1)*ND];
__device__ float  g_OffP[BHD*NCH*ND];
__device__ float  g_opn[BHD*(NCH+1)];
__device__ float  g_opp[BHD*NCH];
__device__ int    g_lo [BHD*NN];
__device__ float2 g_f12[BHD*NN];         // (exp(w1), exp(0.2*w1))

__device__ __forceinline__ float warp_incl_scan(float v, int lane) {
    #pragma unroll
    for (int o = 1; o < 32; o <<= 1) {
        float u = __shfl_up_sync(0xffffffffu, v, o);
        if (lane >= o) v += u;
    }
    return v;
}

// ---------------- kernel 1: Wh = x @ W[h], Wh1 = Wh.a1, Wh2 = Wh.a2 ----------------
// 4 rows per warp, register-blocked
__global__ void __launch_bounds__(256) k1(const float* __restrict__ x,
                                          const float* __restrict__ W,
                                          const float* __restrict__ a) {
    __shared__ float Ws[FIN*ND];
    __shared__ float a1s[ND], a2s[ND];
    const int h = blockIdx.y, b = blockIdx.z;
    const int tid = threadIdx.x;
    for (int i = tid; i < FIN*ND; i += 256) Ws[i] = W[h*FIN*ND + i];
    if (tid < 2*ND) {
        float v = a[h*2*ND + tid];
        if (tid < ND) a1s[tid] = v; else a2s[tid-ND] = v;
    }
    __syncthreads();

    const int warp = tid >> 5, lane = tid & 31;
    const int n0 = blockIdx.x * 32 + warp * 4;
    const float* xr = x + ((size_t)(b*NN + n0))*FIN;

    float xv[4][4];
    #pragma unroll
    for (int r = 0; r < 4; r++)
        #pragma unroll
        for (int q = 0; q < 4; q++)
            xv[r][q] = xr[r*FIN + q*32 + lane];

    float acc[4] = {0.f, 0.f, 0.f, 0.f};
    #pragma unroll
    for (int k = 0; k < FIN; k++) {
        float w = Ws[k*ND + lane];
        #pragma unroll
        for (int r = 0; r < 4; r++) {
            float xb = __shfl_sync(0xffffffffu, xv[r][k >> 5], k & 31);
            acc[r] = fmaf(xb, w, acc[r]);
        }
    }
    const int bh = b*NH + h;
    #pragma unroll
    for (int r = 0; r < 4; r++)
        g_Wh[((size_t)(bh*NN + n0 + r))*ND + lane] = acc[r];

    #pragma unroll
    for (int r = 0; r < 4; r++) {
        float t1 = acc[r] * a1s[lane], t2 = acc[r] * a2s[lane];
        #pragma unroll
        for (int o = 16; o; o >>= 1) {
            t1 += __shfl_xor_sync(0xffffffffu, t1, o);
            t2 += __shfl_xor_sync(0xffffffffu, t2, o);
        }
        if (lane == 0) { g_Wh1[bh*NN + n0 + r] = t1; g_Wh2[bh*NN + n0 + r] = t2; }
    }
}

// ---------------- kernel 2: rank-by-counting "sort" ----------------
__global__ void __launch_bounds__(128) k2rank() {
    __shared__ float4 w2v[NN/4];
    const int bh = blockIdx.y;
    const int tid = threadIdx.x;
    const float* w2 = g_Wh2 + bh*NN;
    for (int j = tid; j < NN/4; j += 128) w2v[j] = ((const float4*)w2)[j];
    __syncthreads();
    const int i = blockIdx.x*128 + tid;
    const float vi = ((const float*)w2v)[i];
    int rank = 0;
    #pragma unroll 8
    for (int j4 = 0; j4 < NN/4; j4++) {
        float4 v = w2v[j4];
        int j = j4*4;
        rank += (v.x < vi) || (v.x == vi && (j+0) < i);
        rank += (v.y < vi) || (v.y == vi && (j+1) < i);
        rank += (v.z < vi) || (v.z == vi && (j+2) < i);
        rank += (v.w < vi) || (v.w == vi && (j+3) < i);
    }
    g_perm[bh*NN + rank] = i;
    g_w2s [bh*NN + rank] = vi;
}

// ---------------- kernel 3: per-chunk local scans + chunk totals ----------------
__global__ void __launch_bounds__(1024) k3() {
    __shared__ float tA[CHSZ][ND+1];
    __shared__ float tB[CHSZ][ND+1];
    __shared__ float ewn[CHSZ], ewp[CHSZ];
    __shared__ int   pr[CHSZ];
    const int c = blockIdx.x, bh = blockIdx.y;
    const int tid = threadIdx.x, warp = tid >> 5, lane = tid & 31;
    const int base = bh*NN + c*CHSZ;

    if (tid < CHSZ) {
        float v = g_w2s[base + tid];
        ewn[tid] = expf(0.2f * v);
        ewp[tid] = expf(v);
        pr[tid]  = g_perm[base + tid];
    }
    __syncthreads();
    #pragma unroll
    for (int q = 0; q < 4; q++) {
        int r = warp + q*32;
        tA[r][lane] = g_Wh[((size_t)(bh*NN) + pr[r])*ND + lane];
    }
    __syncthreads();

    // forward neg scan (exclusive), warp = channel
    {
        float carry = 0.f;
        #pragma unroll
        for (int s = 0; s < 4; s++) {
            int j = s*32 + lane;
            float v = ewn[j] * tA[j][warp];
            float inc = warp_incl_scan(v, lane);
            float exc = __shfl_up_sync(0xffffffffu, inc, 1);
            if (lane == 0) exc = 0.f;
            tB[j][warp] = carry + exc;
            carry += __shfl_sync(0xffffffffu, inc, 31);
        }
        if (lane == 0) g_CnegT[(bh*NCH + c)*ND + warp] = carry;
    }
    __syncthreads();
    #pragma unroll
    for (int q = 0; q < 4; q++) {
        int r = warp + q*32;
        g_SnegL[((size_t)base + r)*ND + lane] = tB[r][lane];
    }
    __syncthreads();

    // backward pos scan (inclusive suffix)
    {
        float carry = 0.f;
        #pragma unroll
        for (int s = 3; s >= 0; s--) {
            int j = s*32 + (31 - lane);
            float v = ewp[j] * tA[j][warp];
            float inc = warp_incl_scan(v, lane);
            tB[j][warp] = carry + inc;
            carry += __shfl_sync(0xffffffffu, inc, 31);
        }
        if (lane == 0) g_CposT[(bh*NCH + c)*ND + warp] = carry;
    }
    __syncthreads();
    #pragma unroll
    for (int q = 0; q < 4; q++) {
        int r = warp + q*32;
        g_SposL[((size_t)base + r)*ND + lane] = tB[r][lane];
    }

    // scalar local scans (warps 0 and 1)
    if (warp == 0) {
        float carry = 0.f;
        #pragma unroll
        for (int s = 0; s < 4; s++) {
            int j = s*32 + lane;
            float inc = warp_incl_scan(ewn[j], lane);
            float exc = __shfl_up_sync(0xffffffffu, inc, 1);
            if (lane == 0) exc = 0.f;
            g_pnL[base + j] = carry + exc;
            carry += __shfl_sync(0xffffffffu, inc, 31);
        }
        if (lane == 0) g_pnT[bh*NCH + c] = carry;
    } else if (warp == 1) {
        float carry = 0.f;
        #pragma unroll
        for (int s = 3; s >= 0; s--) {
            int j = s*32 + (31 - lane);
            float inc = warp_incl_scan(ewp[j], lane);
            g_ppL[base + j] = carry + inc;
            carry += __shfl_sync(0xffffffffu, inc, 31);
        }
        if (lane == 0) g_ppT[bh*NCH + c] = carry;
    }
}

// ---------------- kernel 3b: chunk-total offsets to global ----------------
__global__ void __launch_bounds__(96) k3b() {
    const int bh = blockIdx.x;
    const int tid = threadIdx.x;
    if (tid < 32) {
        float s = 0.f;
        #pragma unroll
        for (int c = 0; c < NCH; c++) {
            g_OffN[(bh*(NCH+1) + c)*ND + tid] = s;
            s += g_CnegT[(bh*NCH + c)*ND + tid];
        }
        g_OffN[(bh*(NCH+1) + NCH)*ND + tid] = s;
    } else if (tid < 64) {
        int ch = tid - 32;
        float s = 0.f;
        #pragma unroll
        for (int c = NCH-1; c >= 0; c--) {
            g_OffP[(bh*NCH + c)*ND + ch] = s;
            s += g_CposT[(bh*NCH + c)*ND + ch];
        }
    } else if (tid == 64) {
        float s = 0.f;
        #pragma unroll
        for (int c = 0; c < NCH; c++) { g_opn[bh*(NCH+1) + c] = s; s += g_pnT[bh*NCH + c]; }
        g_opn[bh*(NCH+1) + NCH] = s;
    } else if (tid == 65) {
        float s = 0.f;
        #pragma unroll
        for (int c = NCH-1; c >= 0; c--) { g_opp[bh*NCH + c] = s; s += g_ppT[bh*NCH + c]; }
    }
}

// ---------------- kernel 4: per-row threshold search + exp factors ----------------
__global__ void __launch_bounds__(128) k4() {
    const int bh = blockIdx.y;
    const int i = blockIdx.x*128 + threadIdx.x;
    const float w1 = g_Wh1[bh*NN + i];
    const float thr = -w1;
    const float* w2s = g_w2s + bh*NN;
    int lo = 0, hi = NN;
    #pragma unroll
    for (int it = 0; it < 11; it++) {
        int mid = (lo + hi) >> 1;
        if (mid < hi) { if (w2s[mid] <= thr) lo = mid + 1; else hi = mid; }
    }
    g_lo[bh*NN + i] = lo;
    g_f12[bh*NN + i] = make_float2(expf(w1), expf(0.2f * w1));
}

// ---------------- kernel 5: per-row combine (warp per row, 4 rows/warp) ----------------
__global__ void __launch_bounds__(256) k5(float* __restrict__ out) {
    const int bh = blockIdx.y;
    const int b = bh >> 2, h = bh & 3;
    const int tid = threadIdx.x, warp = tid >> 5, lane = tid & 31;
    const int i0 = blockIdx.x*32 + warp*4;

    #pragma unroll
    for (int r = 0; r < 4; r++) {
        const int i = i0 + r;
        const int lo = g_lo[bh*NN + i];
        const float2 f = g_f12[bh*NN + i];
        float sneg, spos, pn, pp;
        if (lo < NN) {
            const int c = lo >> 7;
            const size_t ix = ((size_t)(bh*NN) + lo)*ND + lane;
            sneg = g_SnegL[ix] + g_OffN[(bh*(NCH+1) + c)*ND + lane];
            spos = g_SposL[ix] + g_OffP[(bh*NCH + c)*ND + lane];
            pn   = g_pnL[bh*NN + lo] + g_opn[bh*(NCH+1) + c];
            pp   = g_ppL[bh*NN + lo] + g_opp[bh*NCH + c];
        } else {
            sneg = g_OffN[(bh*(NCH+1) + NCH)*ND + lane];
            spos = 0.f;
            pn   = g_opn[bh*(NCH+1) + NCH];
            pp   = 0.f;
        }
        float num = f.y*sneg + f.x*spos;
        float den = f.y*pn + f.x*pp;
        float hv = num / den;
        float res = hv > 0.f ? hv : expm1f(hv);
        out[((size_t)(b*NN + i))*(NH*ND) + h*ND + lane] = res;
    }
}

extern "C" void kernel_launch(void* const* d_in, const int* in_sizes, int n_in,
                              void* d_out, int out_size) {
    (void)in_sizes; (void)n_in; (void)out_size;
    const float* x = (const float*)d_in[0];
    const float* W = (const float*)d_in[1];
    const float* a = (const float*)d_in[2];
    float* out = (float*)d_out;

    k1<<<dim3(NN/32, NH, NB), 256>>>(x, W, a);
    k2rank<<<dim3(NN/128, BHD), 128>>>();
    k3<<<dim3(NCH, BHD), 1024>>>();
    k4<<<dim3(NN/128, BHD), 128>>>();
    k3b<<<BHD, 96>>>();
    k5<<<dim3(NN/32, BHD), 256>>>(out);
}

// round 4
// speedup vs baseline: 3.3553x; 1.1678x over previous
#include <cuda_runtime.h>

#define NB   4
#define NH   4
#define NN   2048
#define FIN  128
#define ND   32
#define BHD  (NB*NH)
#define NCH  16      // chunks per (b,h)
#define CHSZ 128     // rows per chunk

// scratch (device globals; no allocation allowed)
__device__ float  g_Wh  [BHD*NN*ND];
__device__ float  g_Wh1 [BHD*NN];
__device__ float  g_Wh2 [BHD*NN];
__device__ int    g_perm[BHD*NN];        // sorted pos -> original row
__device__ float  g_w2s [BHD*NN];        // sorted w2 keys
__device__ float  g_SnegL[BHD*NN*ND];    // per-chunk exclusive prefix of exp(.2 w2)*Wh
__device__ float  g_SposL[BHD*NN*ND];    // per-chunk inclusive suffix of exp(w2)*Wh
__device__ float  g_CnegT[BHD*NCH*ND];   // chunk total vectors
__device__ float  g_CposT[BHD*NCH*ND];
__device__ float  g_pnL[BHD*NN];         // scalar local prefix/suffix
__device__ float  g_ppL[BHD*NN];
__device__ float  g_pnT[BHD*NCH];        // scalar chunk totals
__device__ float  g_ppT[BHD*NCH];

__device__ __forceinline__ float warp_incl_scan(float v, int lane) {
    #pragma unroll
    for (int o = 1; o < 32; o <<= 1) {
        float u = __shfl_up_sync(0xffffffffu, v, o);
        if (lane >= o) v += u;
    }
    return v;
}

// ---------------- kernel 1: Wh = x @ W[h], Wh1 = Wh.a1, Wh2 = Wh.a2 ----------------
__global__ void __launch_bounds__(256) k1(const float* __restrict__ x,
                                          const float* __restrict__ W,
                                          const float* __restrict__ a) {
    __shared__ float Ws[FIN*ND];
    __shared__ float a1s[ND], a2s[ND];
    const int h = blockIdx.y, b = blockIdx.z;
    const int tid = threadIdx.x;
    for (int i = tid; i < FIN*ND; i += 256) Ws[i] = W[h*FIN*ND + i];
    if (tid < 2*ND) {
        float v = a[h*2*ND + tid];
        if (tid < ND) a1s[tid] = v; else a2s[tid-ND] = v;
    }
    __syncthreads();

    const int warp = tid >> 5, lane = tid & 31;
    const int n0 = blockIdx.x * 32 + warp * 4;
    const float* xr = x + ((size_t)(b*NN + n0))*FIN;

    float xv[4][4];
    #pragma unroll
    for (int r = 0; r < 4; r++)
        #pragma unroll
        for (int q = 0; q < 4; q++)
            xv[r][q] = xr[r*FIN + q*32 + lane];

    float acc[4] = {0.f, 0.f, 0.f, 0.f};
    #pragma unroll
    for (int k = 0; k < FIN; k++) {
        float w = Ws[k*ND + lane];
        #pragma unroll
        for (int r = 0; r < 4; r++) {
            float xb = __shfl_sync(0xffffffffu, xv[r][k >> 5], k & 31);
            acc[r] = fmaf(xb, w, acc[r]);
        }
    }
    const int bh = b*NH + h;
    #pragma unroll
    for (int r = 0; r < 4; r++)
        g_Wh[((size_t)(bh*NN + n0 + r))*ND + lane] = acc[r];

    #pragma unroll
    for (int r = 0; r < 4; r++) {
        float t1 = acc[r] * a1s[lane], t2 = acc[r] * a2s[lane];
        #pragma unroll
        for (int o = 16; o; o >>= 1) {
            t1 += __shfl_xor_sync(0xffffffffu, t1, o);
            t2 += __shfl_xor_sync(0xffffffffu, t2, o);
        }
        if (lane == 0) { g_Wh1[bh*NN + n0 + r] = t1; g_Wh2[bh*NN + n0 + r] = t2; }
    }
}

// ---------------- kernel 2: bitonic sort of packed (key|idx), one block per bh ----------------
__global__ void __launch_bounds__(1024) k2sort() {
    __shared__ unsigned long long kv[NN];
    const int bh = blockIdx.x;
    const int tid = threadIdx.x;

    for (int e = tid; e < NN; e += 1024) {
        unsigned u = __float_as_uint(g_Wh2[bh*NN + e]);
        u = (u & 0x80000000u) ? ~u : (u | 0x80000000u);   // order-preserving uint
        kv[e] = ((unsigned long long)u << 32) | (unsigned)e;
    }
    __syncthreads();

    for (int k = 2; k <= NN; k <<= 1) {
        int s = k >> 1;
        // strides >= 32: cross-warp, need block barrier
        for (; s >= 32; s >>= 1) {
            #pragma unroll
            for (int tt = 0; tt < 2; tt++) {
                int t = tid + tt*1024;
                int j = t ^ s;
                if (j > t) {
                    unsigned long long va = kv[t], vb = kv[j];
                    bool up = ((t & k) == 0);
                    if ((va > vb) == up) { kv[t] = vb; kv[j] = va; }
                }
            }
            __syncthreads();
        }
        // strides < 32: partner element handled within the same warp
        for (; s >= 1; s >>= 1) {
            #pragma unroll
            for (int tt = 0; tt < 2; tt++) {
                int t = tid + tt*1024;
                int j = t ^ s;
                if (j > t) {
                    unsigned long long va = kv[t], vb = kv[j];
                    bool up = ((t & k) == 0);
                    if ((va > vb) == up) { kv[t] = vb; kv[j] = va; }
                }
            }
            __syncwarp();
        }
        __syncthreads();
    }

    for (int e = tid; e < NN; e += 1024) {
        unsigned long long v = kv[e];
        unsigned u = (unsigned)(v >> 32);
        u = (u & 0x80000000u) ? (u & 0x7fffffffu) : ~u;   // inverse transform
        g_w2s [bh*NN + e] = __uint_as_float(u);
        g_perm[bh*NN + e] = (int)(v & 0xffffffffu);
    }
}

// ---------------- kernel 3: per-chunk local scans + chunk totals ----------------
__global__ void __launch_bounds__(1024) k3() {
    __shared__ float tA[CHSZ][ND+1];
    __shared__ float tB[CHSZ][ND+1];
    __shared__ float ewn[CHSZ], ewp[CHSZ];
    __shared__ int   pr[CHSZ];
    const int c = blockIdx.x, bh = blockIdx.y;
    const int tid = threadIdx.x, warp = tid >> 5, lane = tid & 31;
    const int base = bh*NN + c*CHSZ;

    if (tid < CHSZ) {
        float v = g_w2s[base + tid];
        ewn[tid] = expf(0.2f * v);
        ewp[tid] = expf(v);
        pr[tid]  = g_perm[base + tid];
    }
    __syncthreads();
    #pragma unroll
    for (int q = 0; q < 4; q++) {
        int r = warp + q*32;
        tA[r][lane] = g_Wh[((size_t)(bh*NN) + pr[r])*ND + lane];
    }
    __syncthreads();

    // forward neg scan (exclusive), warp = channel
    {
        float carry = 0.f;
        #pragma unroll
        for (int s = 0; s < 4; s++) {
            int j = s*32 + lane;
            float v = ewn[j] * tA[j][warp];
            float inc = warp_incl_scan(v, lane);
            float exc = __shfl_up_sync(0xffffffffu, inc, 1);
            if (lane == 0) exc = 0.f;
            tB[j][warp] = carry + exc;
            carry += __shfl_sync(0xffffffffu, inc, 31);
        }
        if (lane == 0) g_CnegT[(bh*NCH + c)*ND + warp] = carry;
    }
    __syncthreads();
    #pragma unroll
    for (int q = 0; q < 4; q++) {
        int r = warp + q*32;
        g_SnegL[((size_t)base + r)*ND + lane] = tB[r][lane];
    }
    __syncthreads();

    // backward pos scan (inclusive suffix)
    {
        float carry = 0.f;
        #pragma unroll
        for (int s = 3; s >= 0; s--) {
            int j = s*32 + (31 - lane);
            float v = ewp[j] * tA[j][warp];
            float inc = warp_incl_scan(v, lane);
            tB[j][warp] = carry + inc;
            carry += __shfl_sync(0xffffffffu, inc, 31);
        }
        if (lane == 0) g_CposT[(bh*NCH + c)*ND + warp] = carry;
    }
    __syncthreads();
    #pragma unroll
    for (int q = 0; q < 4; q++) {
        int r = warp + q*32;
        g_SposL[((size_t)base + r)*ND + lane] = tB[r][lane];
    }

    // scalar local scans (warps 0 and 1)
    if (warp == 0) {
        float carry = 0.f;
        #pragma unroll
        for (int s = 0; s < 4; s++) {
            int j = s*32 + lane;
            float inc = warp_incl_scan(ewn[j], lane);
            float exc = __shfl_up_sync(0xffffffffu, inc, 1);
            if (lane == 0) exc = 0.f;
            g_pnL[base + j] = carry + exc;
            carry += __shfl_sync(0xffffffffu, inc, 31);
        }
        if (lane == 0) g_pnT[bh*NCH + c] = carry;
    } else if (warp == 1) {
        float carry = 0.f;
        #pragma unroll
        for (int s = 3; s >= 0; s--) {
            int j = s*32 + (31 - lane);
            float inc = warp_incl_scan(ewp[j], lane);
            g_ppL[base + j] = carry + inc;
            carry += __shfl_sync(0xffffffffu, inc, 31);
        }
        if (lane == 0) g_ppT[bh*NCH + c] = carry;
    }
}

// ---------------- kernel 5: fused offsets + search + combine ----------------
__global__ void __launch_bounds__(256) k5f(float* __restrict__ out) {
    __shared__ float keys[NN];
    __shared__ float OffN[(NCH+1)*ND];
    __shared__ float OffP[NCH*ND];
    __shared__ float opn[NCH+1], opp[NCH];
    const int bh = blockIdx.y;
    const int b = bh >> 2, h = bh & 3;
    const int tid = threadIdx.x, warp = tid >> 5, lane = tid & 31;

    for (int j = tid; j < NN; j += 256) keys[j] = g_w2s[bh*NN + j];
    if (tid < ND) {
        float s = 0.f;
        #pragma unroll
        for (int c = 0; c < NCH; c++) { OffN[c*ND + tid] = s; s += g_CnegT[(bh*NCH + c)*ND + tid]; }
        OffN[NCH*ND + tid] = s;
    } else if (tid < 2*ND) {
        int ch = tid - ND;
        float s = 0.f;
        #pragma unroll
        for (int c = NCH-1; c >= 0; c--) { OffP[c*ND + ch] = s; s += g_CposT[(bh*NCH + c)*ND + ch]; }
    } else if (tid == 2*ND) {
        float s = 0.f;
        #pragma unroll
        for (int c = 0; c < NCH; c++) { opn[c] = s; s += g_pnT[bh*NCH + c]; }
        opn[NCH] = s;
    } else if (tid == 2*ND + 1) {
        float s = 0.f;
        #pragma unroll
        for (int c = NCH-1; c >= 0; c--) { opp[c] = s; s += g_ppT[bh*NCH + c]; }
    }
    __syncthreads();

    const int i0 = blockIdx.x*32 + warp*4;

    // lanes 0..3 each search one row; results broadcast via shfl
    int   lo_l = 0;
    float f1_l = 0.f, f2_l = 0.f;
    if (lane < 4) {
        float w1 = g_Wh1[bh*NN + i0 + lane];
        float thr = -w1;
        int lo = 0, hi = NN;
        #pragma unroll
        for (int it = 0; it < 11; it++) {
            int mid = (lo + hi) >> 1;
            if (mid < hi) { if (keys[mid] <= thr) lo = mid + 1; else hi = mid; }
        }
        lo_l = lo;
        f1_l = expf(w1);
        f2_l = expf(0.2f * w1);
    }

    #pragma unroll
    for (int r = 0; r < 4; r++) {
        const int i  = i0 + r;
        const int lo = __shfl_sync(0xffffffffu, lo_l, r);
        const float f1 = __shfl_sync(0xffffffffu, f1_l, r);
        const float f2 = __shfl_sync(0xffffffffu, f2_l, r);
        float sneg, spos, pn, pp;
        if (lo < NN) {
            const int c = lo >> 7;
            const size_t ix = ((size_t)(bh*NN) + lo)*ND + lane;
            sneg = g_SnegL[ix] + OffN[c*ND + lane];
            spos = g_SposL[ix] + OffP[c*ND + lane];
            pn   = g_pnL[bh*NN + lo] + opn[c];
            pp   = g_ppL[bh*NN + lo] + opp[c];
        } else {
            sneg = OffN[NCH*ND + lane];
            spos = 0.f;
            pn   = opn[NCH];
            pp   = 0.f;
        }
        float num = f2*sneg + f1*spos;
        float den = f2*pn + f1*pp;
        float hv = num / den;
        float res = hv > 0.f ? hv : expm1f(hv);
        out[((size_t)(b*NN + i))*(NH*ND) + h*ND + lane] = res;
    }
}

extern "C" void kernel_launch(void* const* d_in, const int* in_sizes, int n_in,
                              void* d_out, int out_size) {
    (void)in_sizes; (void)n_in; (void)out_size;
    const float* x = (const float*)d_in[0];
    const float* W = (const float*)d_in[1];
    const float* a = (const float*)d_in[2];
    float* out = (float*)d_out;

    k1<<<dim3(NN/32, NH, NB), 256>>>(x, W, a);
    k2sort<<<BHD, 1024>>>();
    k3<<<dim3(NCH, BHD), 1024>>>();
    k5f<<<dim3(NN/32, BHD), 256>>>(out);
}